// round 14
// baseline (speedup 1.0000x reference)
#include <cuda_runtime.h>
#include <cuda_bf16.h>

// LightCSCF: bpr + reg + cscf losses.
// total = e1@e2^T + e1@e1^T = e1 @ (e1+e2)^T -> 8192x8192x64 bf16 tensor GEMM,
// fused epilogue + row-sum:  g(x) = t + C*max(e^4, t), t = ex2(acc), C = e^-4.
// R14 (vs R13): occupancy 4 -> 5 CTA/SM. Register diet: A-frags reloaded per
// column-group (af 32->8 live regs), epilogue sums fused via fmaf (8->4 regs),
// __launch_bounds__(256,5). Prep + fast rowloss unchanged.

#define BATCH 8192
#define DIM   64
#define NPLANE 128           // 64-col stripes = partial planes

#define SCALE_A 7.2134752044f      // 5 * log2(e)
#define C_MARG  0.0183156393f      // exp(-4)
#define INV_C   54.598150033f      // exp(+4)

__device__ __nv_bfloat16 g_e1h[BATCH * DIM];
__device__ __nv_bfloat16 g_fh [BATCH * DIM];
__device__ float g_pos[BATCH];
__device__ float g_bpr[BATCH];
__device__ float g_sq [BATCH];
__device__ float g_partial[NPLANE * BATCH];  // [stripe][row]
__device__ float g_blk[64 * 3];
__device__ unsigned g_ctr = 0;

__device__ __forceinline__ unsigned smem_u32(const void* p) {
    return (unsigned)__cvta_generic_to_shared(p);
}
__device__ __forceinline__ float ex2f(float x) {
    float y; asm("ex2.approx.f32 %0, %1;" : "=f"(y) : "f"(x)); return y;
}
__device__ __forceinline__ void cp16(unsigned dst, const void* src) {
    asm volatile("cp.async.cg.shared.global [%0], [%1], 16;" :: "r"(dst), "l"(src));
}
__device__ __forceinline__ void cp_commit() { asm volatile("cp.async.commit_group;"); }
__device__ __forceinline__ void cp_wait0()  { asm volatile("cp.async.wait_group 0;"); }
__device__ __forceinline__ void cp_wait1()  { asm volatile("cp.async.wait_group 1;"); }

// ---------------------------------------------------------------------------
// Kernel 1: gather + per-row stats + bf16 operand tables. 2 rows per warp.
// ---------------------------------------------------------------------------
__global__ void __launch_bounds__(128) prep_kernel(
    const float* __restrict__ ut, const float* __restrict__ it,
    const int* __restrict__ user, const int* __restrict__ pos,
    const int* __restrict__ neg)
{
    int wid  = threadIdx.x >> 5;
    int lane = threadIdx.x & 31;
    int r0 = blockIdx.x * 8 + wid * 2;
    int r1 = r0 + 1;

    const float2* u0p = (const float2*)(ut + (long long)user[r0] * DIM);
    const float2* u1p = (const float2*)(ut + (long long)user[r1] * DIM);
    const float2* p0p = (const float2*)(it + (long long)pos[r0]  * DIM);
    const float2* p1p = (const float2*)(it + (long long)pos[r1]  * DIM);
    const float2* n0p = (const float2*)(it + (long long)neg[r0]  * DIM);
    const float2* n1p = (const float2*)(it + (long long)neg[r1]  * DIM);
    float2 u0 = u0p[lane], u1 = u1p[lane];
    float2 p0 = p0p[lane], p1 = p1p[lane];
    float2 n0 = n0p[lane], n1 = n1p[lane];

    float up0 = u0.x*p0.x + u0.y*p0.y, up1 = u1.x*p1.x + u1.y*p1.y;
    float un0 = u0.x*n0.x + u0.y*n0.y, un1 = u1.x*n1.x + u1.y*n1.y;
    float uu0 = u0.x*u0.x + u0.y*u0.y, uu1 = u1.x*u1.x + u1.y*u1.y;
    float pp0 = p0.x*p0.x + p0.y*p0.y, pp1 = p1.x*p1.x + p1.y*p1.y;
    float nn0 = n0.x*n0.x + n0.y*n0.y, nn1 = n1.x*n1.x + n1.y*n1.y;

    #pragma unroll
    for (int off = 16; off; off >>= 1) {
        up0 += __shfl_xor_sync(~0u, up0, off); up1 += __shfl_xor_sync(~0u, up1, off);
        un0 += __shfl_xor_sync(~0u, un0, off); un1 += __shfl_xor_sync(~0u, un1, off);
        uu0 += __shfl_xor_sync(~0u, uu0, off); uu1 += __shfl_xor_sync(~0u, uu1, off);
        pp0 += __shfl_xor_sync(~0u, pp0, off); pp1 += __shfl_xor_sync(~0u, pp1, off);
        nn0 += __shfl_xor_sync(~0u, nn0, off); nn1 += __shfl_xor_sync(~0u, nn1, off);
    }

    float inu0 = 1.0f / fmaxf(sqrtf(uu0), 1e-12f);
    float inu1 = 1.0f / fmaxf(sqrtf(uu1), 1e-12f);
    float inp0 = 1.0f / fmaxf(sqrtf(pp0), 1e-12f);
    float inp1 = 1.0f / fmaxf(sqrtf(pp1), 1e-12f);

    float ax0 = u0.x * inu0, ay0 = u0.y * inu0;
    float ax1 = u1.x * inu1, ay1 = u1.y * inu1;
    ((__nv_bfloat162*)(g_e1h + r0 * DIM))[lane] =
        __floats2bfloat162_rn(ax0 * SCALE_A, ay0 * SCALE_A);
    ((__nv_bfloat162*)(g_e1h + r1 * DIM))[lane] =
        __floats2bfloat162_rn(ax1 * SCALE_A, ay1 * SCALE_A);
    ((__nv_bfloat162*)(g_fh + r0 * DIM))[lane] =
        __floats2bfloat162_rn(ax0 + p0.x * inp0, ay0 + p0.y * inp0);
    ((__nv_bfloat162*)(g_fh + r1 * DIM))[lane] =
        __floats2bfloat162_rn(ax1 + p1.x * inp1, ay1 + p1.y * inp1);

    if (lane == 0) {
        float sim0 = up0 * inu0 * inp0, sim1 = up1 * inu1 * inp1;
        float t0 = __expf(sim0 * 5.0f), t1 = __expf(sim1 * 5.0f);
        g_pos[r0] = t0 + fmaxf(1.0f, t0 * C_MARG);
        g_pos[r1] = t1 + fmaxf(1.0f, t1 * C_MARG);
        float x0 = up0 - un0, x1 = up1 - un1;
        g_bpr[r0] = fminf(x0, 0.0f) - log1pf(__expf(-fabsf(x0)));
        g_bpr[r1] = fminf(x1, 0.0f) - log1pf(__expf(-fabsf(x1)));
        g_sq[r0] = uu0 + pp0 + nn0;
        g_sq[r1] = uu1 + pp1 + nn1;
    }
}

// ---------------------------------------------------------------------------
// Kernel 2: tensor GEMM + fused epilogue + row-sum.
// grid (64, 64). CTA: 128 rows x two 64-col tiles. Warp w: rows (w&3)*32,
// tile (w>>2). A frags reloaded per column-group (low regs). Warps 4-7 load
// B1 under tile-0 compute. 5 CTAs/SM.
// ---------------------------------------------------------------------------
__global__ void __launch_bounds__(256, 5) gemm_kernel()
{
    __shared__ __align__(128) __nv_bfloat16 a_s[128 * DIM];     // 16KB
    __shared__ __align__(128) __nv_bfloat16 b_s[2][64 * DIM];   // 2 x 8KB

    int tid = threadIdx.x;
    int rowBase = blockIdx.y * 128;
    int cb0 = blockIdx.x * 2;

    unsigned a_base = smem_u32(a_s);
    unsigned b_base[2] = { smem_u32(b_s[0]), smem_u32(b_s[1]) };

    // Stage. Group A (all threads): A tile + B0. Group B (warps 4-7): B1.
    {
        const char* ga  = (const char*)(g_e1h + rowBase * DIM);
        const char* gb0 = (const char*)(g_fh + (cb0 * 64) * DIM);
        #pragma unroll
        for (int l = 0; l < 4; l++) {
            int i = tid + l * 256;            // 0..1023
            int r = i >> 3, c = i & 7;
            unsigned soff = (unsigned)(r * 128 + ((c ^ (r & 7)) << 4));
            cp16(a_base + soff, ga + r * 128 + c * 16);
        }
        #pragma unroll
        for (int l = 0; l < 2; l++) {
            int i = tid + l * 256;            // 0..511
            int r = i >> 3, c = i & 7;
            unsigned soff = (unsigned)(r * 128 + ((c ^ (r & 7)) << 4));
            cp16(b_base[0] + soff, gb0 + r * 128 + c * 16);
        }
        cp_commit();

        if (tid >= 128) {                     // warps 4-7 load B1
            const char* gb1 = (const char*)(g_fh + ((cb0 + 1) * 64) * DIM);
            int t2 = tid - 128;
            #pragma unroll
            for (int l = 0; l < 4; l++) {
                int i = t2 + l * 128;         // 0..511
                int r = i >> 3, c = i & 7;
                unsigned soff = (unsigned)(r * 128 + ((c ^ (r & 7)) << 4));
                cp16(b_base[1] + soff, gb1 + r * 128 + c * 16);
            }
            cp_commit();
            cp_wait1();                        // A+B0 done (B1 still flying)
        } else {
            cp_wait0();                        // only group = A+B0
        }
    }
    __syncthreads();                           // A+B0 visible to all

    int wid  = tid >> 5;
    int lane = tid & 31;
    int wy   = wid & 3;        // row-group: rows wy*32 .. +31
    int tile = wid >> 2;       // 0 or 1
    int lr = lane & 15;
    int h  = lane >> 4;
    int x7 = lane & 7;
    int bcol = lane & 7;
    int kh = (lane >> 3) & 1;

    int wbase = wy * 32;
    unsigned a_row0 = a_base + (wbase + lr) * 128;        // mf0 rows
    unsigned a_row1 = a_row0 + 16 * 128;                  // mf1 rows

    if (tile == 1) {
        cp_wait0();                            // B1 landed
        asm volatile("bar.sync 1, 128;" ::: "memory");  // warps 4-7 only
    }
    unsigned bt = b_base[tile];

    float v0 = 0.f, v1 = 0.f, v2 = 0.f, v3 = 0.f;   // per-row partial sums

    #pragma unroll
    for (int g = 0; g < 8; g++) {             // 8 column-groups of 8
        float acc[2][4];
        #pragma unroll
        for (int mf = 0; mf < 2; mf++)
            #pragma unroll
            for (int q = 0; q < 4; q++) acc[mf][q] = 0.0f;

        unsigned b_row = bt + (g * 8 + bcol) * 128;
        #pragma unroll
        for (int s = 0; s < 4; s++) {
            unsigned swa = (unsigned)(((2 * s + h) ^ x7) << 4);
            unsigned swb = (unsigned)(((2 * s + kh) ^ x7) << 4);

            unsigned r0, r1;
            asm volatile("ldmatrix.sync.aligned.m8n8.x2.shared.b16 "
                         "{%0,%1}, [%2];"
                         : "=r"(r0), "=r"(r1)
                         : "r"(b_row + swb));

            unsigned a0, a1, a2, a3;
            asm volatile("ldmatrix.sync.aligned.m8n8.x4.shared.b16 "
                         "{%0,%1,%2,%3}, [%4];"
                         : "=r"(a0), "=r"(a1), "=r"(a2), "=r"(a3)
                         : "r"(a_row0 + swa));
            asm volatile(
                "mma.sync.aligned.m16n8k16.row.col.f32.bf16.bf16.f32 "
                "{%0,%1,%2,%3}, {%4,%5,%6,%7}, {%8,%9}, {%0,%1,%2,%3};"
                : "+f"(acc[0][0]), "+f"(acc[0][1]),
                  "+f"(acc[0][2]), "+f"(acc[0][3])
                : "r"(a0), "r"(a1), "r"(a2), "r"(a3), "r"(r0), "r"(r1));

            asm volatile("ldmatrix.sync.aligned.m8n8.x4.shared.b16 "
                         "{%0,%1,%2,%3}, [%4];"
                         : "=r"(a0), "=r"(a1), "=r"(a2), "=r"(a3)
                         : "r"(a_row1 + swa));
            asm volatile(
                "mma.sync.aligned.m16n8k16.row.col.f32.bf16.bf16.f32 "
                "{%0,%1,%2,%3}, {%4,%5,%6,%7}, {%8,%9}, {%0,%1,%2,%3};"
                : "+f"(acc[1][0]), "+f"(acc[1][1]),
                  "+f"(acc[1][2]), "+f"(acc[1][3])
                : "r"(a0), "r"(a1), "r"(a2), "r"(a3), "r"(r0), "r"(r1));
        }

        // Immediate fused epilogue: v += t + C*max(e^4, t).
        {
            float t;
            t = ex2f(acc[0][0]); v0 += fmaf(fmaxf(INV_C, t), C_MARG, t);
            t = ex2f(acc[0][1]); v0 += fmaf(fmaxf(INV_C, t), C_MARG, t);
            t = ex2f(acc[0][2]); v1 += fmaf(fmaxf(INV_C, t), C_MARG, t);
            t = ex2f(acc[0][3]); v1 += fmaf(fmaxf(INV_C, t), C_MARG, t);
            t = ex2f(acc[1][0]); v2 += fmaf(fmaxf(INV_C, t), C_MARG, t);
            t = ex2f(acc[1][1]); v2 += fmaf(fmaxf(INV_C, t), C_MARG, t);
            t = ex2f(acc[1][2]); v3 += fmaf(fmaxf(INV_C, t), C_MARG, t);
            t = ex2f(acc[1][3]); v3 += fmaf(fmaxf(INV_C, t), C_MARG, t);
        }
    }

    // Reduce across the 4 lanes sharing each row.
    #pragma unroll
    for (int off = 1; off <= 2; off <<= 1) {
        v0 += __shfl_xor_sync(~0u, v0, off);
        v1 += __shfl_xor_sync(~0u, v1, off);
        v2 += __shfl_xor_sync(~0u, v2, off);
        v3 += __shfl_xor_sync(~0u, v3, off);
    }
    if ((lane & 3) == 0) {
        int r = rowBase + wbase + (lane >> 2);
        float* pp = g_partial + (cb0 + tile) * BATCH;
        pp[r]      = v0;
        pp[r + 8]  = v1;
        pp[r + 16] = v2;
        pp[r + 24] = v3;
    }
}

// ---------------------------------------------------------------------------
// Kernel 3: per-row loss + block sums + last-block final.
// block=1024: 8 plane-groups of 16 per row, fixed-order smem combine.
// ---------------------------------------------------------------------------
__global__ void __launch_bounds__(1024) rowloss_final_kernel(float* __restrict__ out)
{
    __shared__ float s[1024];
    __shared__ float sl[128], sb[128], ss[128];
    __shared__ unsigned isLast;

    int tid  = threadIdx.x;
    int lrow = tid & 127;
    int grp  = tid >> 7;                  // 0..7 -> planes grp*16 .. +15
    int row  = blockIdx.x * 128 + lrow;

    float rs = 0.0f;
    #pragma unroll
    for (int p = 0; p < 16; p++)
        rs += g_partial[(grp * 16 + p) * BATCH + row];
    s[tid] = rs;
    __syncthreads();

    if (tid < 128) {
        float tot = 0.0f;
        #pragma unroll
        for (int j = 0; j < 8; j++)       // fixed order
            tot += s[lrow + 128 * j];
        sl[tid] = -logf(g_pos[row] / tot + 1e-5f);
        sb[tid] = g_bpr[row];
        ss[tid] = g_sq[row];
    }
    __syncthreads();
    #pragma unroll
    for (int k = 64; k; k >>= 1) {
        if (tid < k) {
            sl[tid] += sl[tid + k];
            sb[tid] += sb[tid + k];
            ss[tid] += ss[tid + k];
        }
        __syncthreads();
    }

    if (tid == 0) {
        g_blk[blockIdx.x * 3 + 0] = sl[0];
        g_blk[blockIdx.x * 3 + 1] = sb[0];
        g_blk[blockIdx.x * 3 + 2] = ss[0];
        __threadfence();
        isLast = (atomicAdd(&g_ctr, 1u) == (unsigned)(gridDim.x - 1));
    }
    __syncthreads();

    if (isLast) {
        __threadfence();
        if (tid < 32) {
            float l = 0.0f, b = 0.0f, sq = 0.0f;
            for (int i = tid; i < 64; i += 32) {    // fixed order
                l  += g_blk[i * 3 + 0];
                b  += g_blk[i * 3 + 1];
                sq += g_blk[i * 3 + 2];
            }
            #pragma unroll
            for (int off = 16; off; off >>= 1) {
                l  += __shfl_xor_sync(~0u, l, off);
                b  += __shfl_xor_sync(~0u, b, off);
                sq += __shfl_xor_sync(~0u, sq, off);
            }
            if (tid == 0) {
                out[0] = -b / (float)BATCH;
                out[1] = 1e-4f * 0.5f * sq / (float)BATCH;
                out[2] = 0.5f * l / (float)BATCH;
                g_ctr = 0;                          // reset for next replay
            }
        }
    }
}

extern "C" void kernel_launch(void* const* d_in, const int* in_sizes, int n_in,
                              void* d_out, int out_size)
{
    const float* ut  = (const float*)d_in[0];
    const float* it  = (const float*)d_in[1];
    const int* user  = (const int*)d_in[2];
    const int* pos   = (const int*)d_in[3];
    const int* neg   = (const int*)d_in[4];

    prep_kernel<<<BATCH / 8, 128>>>(ut, it, user, pos, neg);
    dim3 grid(64, 64);
    gemm_kernel<<<grid, 256>>>();
    rowloss_final_kernel<<<64, 1024>>>((float*)d_out);
}

// round 15
// speedup vs baseline: 1.0014x; 1.0014x over previous
#include <cuda_runtime.h>
#include <cuda_bf16.h>

// LightCSCF: bpr + reg + cscf losses.
// total = e1@e2^T + e1@e1^T = e1 @ (e1+e2)^T -> 8192x8192x64 bf16 tensor GEMM,
// fused epilogue + row-sum:  g(x) = t + C*max(e^4, t), t = ex2(acc), C = e^-4.
// R15 (vs R13 best): ILP fix. Column-groups processed in PAIRS: per k-step
// one A-frag set (x4 ldmatrix, shared) + two B-frag sets (x2) feed FOUR
// independent mma chains (2 groups x 2 mf). Same LDSM/mma counts as R13 but
// 2x the in-flight chains per warp -> dependency stalls halve. Regs ~50,
// still 4 CTA/SM. Staging/split-warp-B1/rowloss unchanged from R13.

#define BATCH 8192
#define DIM   64
#define NPLANE 128           // 64-col stripes = partial planes

#define SCALE_A 7.2134752044f      // 5 * log2(e)
#define C_MARG  0.0183156393f      // exp(-4)
#define INV_C   54.598150033f      // exp(+4)

__device__ __nv_bfloat16 g_e1h[BATCH * DIM];
__device__ __nv_bfloat16 g_fh [BATCH * DIM];
__device__ float g_pos[BATCH];
__device__ float g_bpr[BATCH];
__device__ float g_sq [BATCH];
__device__ float g_partial[NPLANE * BATCH];  // [stripe][row]
__device__ float g_blk[64 * 3];
__device__ unsigned g_ctr = 0;

__device__ __forceinline__ unsigned smem_u32(const void* p) {
    return (unsigned)__cvta_generic_to_shared(p);
}
__device__ __forceinline__ float ex2f(float x) {
    float y; asm("ex2.approx.f32 %0, %1;" : "=f"(y) : "f"(x)); return y;
}
__device__ __forceinline__ void cp16(unsigned dst, const void* src) {
    asm volatile("cp.async.cg.shared.global [%0], [%1], 16;" :: "r"(dst), "l"(src));
}
__device__ __forceinline__ void cp_commit() { asm volatile("cp.async.commit_group;"); }
__device__ __forceinline__ void cp_wait0()  { asm volatile("cp.async.wait_group 0;"); }
__device__ __forceinline__ void cp_wait1()  { asm volatile("cp.async.wait_group 1;"); }

// ---------------------------------------------------------------------------
// Kernel 1: gather + per-row stats + bf16 operand tables. 2 rows per warp.
// ---------------------------------------------------------------------------
__global__ void __launch_bounds__(128) prep_kernel(
    const float* __restrict__ ut, const float* __restrict__ it,
    const int* __restrict__ user, const int* __restrict__ pos,
    const int* __restrict__ neg)
{
    int wid  = threadIdx.x >> 5;
    int lane = threadIdx.x & 31;
    int r0 = blockIdx.x * 8 + wid * 2;
    int r1 = r0 + 1;

    const float2* u0p = (const float2*)(ut + (long long)user[r0] * DIM);
    const float2* u1p = (const float2*)(ut + (long long)user[r1] * DIM);
    const float2* p0p = (const float2*)(it + (long long)pos[r0]  * DIM);
    const float2* p1p = (const float2*)(it + (long long)pos[r1]  * DIM);
    const float2* n0p = (const float2*)(it + (long long)neg[r0]  * DIM);
    const float2* n1p = (const float2*)(it + (long long)neg[r1]  * DIM);
    float2 u0 = u0p[lane], u1 = u1p[lane];
    float2 p0 = p0p[lane], p1 = p1p[lane];
    float2 n0 = n0p[lane], n1 = n1p[lane];

    float up0 = u0.x*p0.x + u0.y*p0.y, up1 = u1.x*p1.x + u1.y*p1.y;
    float un0 = u0.x*n0.x + u0.y*n0.y, un1 = u1.x*n1.x + u1.y*n1.y;
    float uu0 = u0.x*u0.x + u0.y*u0.y, uu1 = u1.x*u1.x + u1.y*u1.y;
    float pp0 = p0.x*p0.x + p0.y*p0.y, pp1 = p1.x*p1.x + p1.y*p1.y;
    float nn0 = n0.x*n0.x + n0.y*n0.y, nn1 = n1.x*n1.x + n1.y*n1.y;

    #pragma unroll
    for (int off = 16; off; off >>= 1) {
        up0 += __shfl_xor_sync(~0u, up0, off); up1 += __shfl_xor_sync(~0u, up1, off);
        un0 += __shfl_xor_sync(~0u, un0, off); un1 += __shfl_xor_sync(~0u, un1, off);
        uu0 += __shfl_xor_sync(~0u, uu0, off); uu1 += __shfl_xor_sync(~0u, uu1, off);
        pp0 += __shfl_xor_sync(~0u, pp0, off); pp1 += __shfl_xor_sync(~0u, pp1, off);
        nn0 += __shfl_xor_sync(~0u, nn0, off); nn1 += __shfl_xor_sync(~0u, nn1, off);
    }

    float inu0 = 1.0f / fmaxf(sqrtf(uu0), 1e-12f);
    float inu1 = 1.0f / fmaxf(sqrtf(uu1), 1e-12f);
    float inp0 = 1.0f / fmaxf(sqrtf(pp0), 1e-12f);
    float inp1 = 1.0f / fmaxf(sqrtf(pp1), 1e-12f);

    float ax0 = u0.x * inu0, ay0 = u0.y * inu0;
    float ax1 = u1.x * inu1, ay1 = u1.y * inu1;
    ((__nv_bfloat162*)(g_e1h + r0 * DIM))[lane] =
        __floats2bfloat162_rn(ax0 * SCALE_A, ay0 * SCALE_A);
    ((__nv_bfloat162*)(g_e1h + r1 * DIM))[lane] =
        __floats2bfloat162_rn(ax1 * SCALE_A, ay1 * SCALE_A);
    ((__nv_bfloat162*)(g_fh + r0 * DIM))[lane] =
        __floats2bfloat162_rn(ax0 + p0.x * inp0, ay0 + p0.y * inp0);
    ((__nv_bfloat162*)(g_fh + r1 * DIM))[lane] =
        __floats2bfloat162_rn(ax1 + p1.x * inp1, ay1 + p1.y * inp1);

    if (lane == 0) {
        float sim0 = up0 * inu0 * inp0, sim1 = up1 * inu1 * inp1;
        float t0 = __expf(sim0 * 5.0f), t1 = __expf(sim1 * 5.0f);
        g_pos[r0] = t0 + fmaxf(1.0f, t0 * C_MARG);
        g_pos[r1] = t1 + fmaxf(1.0f, t1 * C_MARG);
        float x0 = up0 - un0, x1 = up1 - un1;
        g_bpr[r0] = fminf(x0, 0.0f) - log1pf(__expf(-fabsf(x0)));
        g_bpr[r1] = fminf(x1, 0.0f) - log1pf(__expf(-fabsf(x1)));
        g_sq[r0] = uu0 + pp0 + nn0;
        g_sq[r1] = uu1 + pp1 + nn1;
    }
}

// ---------------------------------------------------------------------------
// Kernel 2: tensor GEMM + fused epilogue + row-sum.
// grid (64, 64). CTA: 128 rows x two 64-col tiles. Warp w: rows (w&3)*32,
// tile (w>>2). Inner loop: 4 pairs of 8-col groups; per k-step one shared
// A-frag set + two B-frag sets -> 4 independent mma chains. 4 CTAs/SM.
// ---------------------------------------------------------------------------
__global__ void __launch_bounds__(256, 4) gemm_kernel()
{
    __shared__ __align__(128) __nv_bfloat16 a_s[128 * DIM];     // 16KB
    __shared__ __align__(128) __nv_bfloat16 b_s[2][64 * DIM];   // 2 x 8KB

    int tid = threadIdx.x;
    int rowBase = blockIdx.y * 128;
    int cb0 = blockIdx.x * 2;

    unsigned a_base = smem_u32(a_s);
    unsigned b_base[2] = { smem_u32(b_s[0]), smem_u32(b_s[1]) };

    // Stage. Group A (all threads): A tile + B0. Group B (warps 4-7): B1.
    {
        const char* ga  = (const char*)(g_e1h + rowBase * DIM);
        const char* gb0 = (const char*)(g_fh + (cb0 * 64) * DIM);
        #pragma unroll
        for (int l = 0; l < 4; l++) {
            int i = tid + l * 256;            // 0..1023
            int r = i >> 3, c = i & 7;
            unsigned soff = (unsigned)(r * 128 + ((c ^ (r & 7)) << 4));
            cp16(a_base + soff, ga + r * 128 + c * 16);
        }
        #pragma unroll
        for (int l = 0; l < 2; l++) {
            int i = tid + l * 256;            // 0..511
            int r = i >> 3, c = i & 7;
            unsigned soff = (unsigned)(r * 128 + ((c ^ (r & 7)) << 4));
            cp16(b_base[0] + soff, gb0 + r * 128 + c * 16);
        }
        cp_commit();

        if (tid >= 128) {                     // warps 4-7 load B1
            const char* gb1 = (const char*)(g_fh + ((cb0 + 1) * 64) * DIM);
            int t2 = tid - 128;
            #pragma unroll
            for (int l = 0; l < 4; l++) {
                int i = t2 + l * 128;         // 0..511
                int r = i >> 3, c = i & 7;
                unsigned soff = (unsigned)(r * 128 + ((c ^ (r & 7)) << 4));
                cp16(b_base[1] + soff, gb1 + r * 128 + c * 16);
            }
            cp_commit();
            cp_wait1();                        // A+B0 done (B1 still flying)
        } else {
            cp_wait0();                        // only group = A+B0
        }
    }
    __syncthreads();                           // A+B0 visible to all

    int wid  = tid >> 5;
    int lane = tid & 31;
    int wy   = wid & 3;        // row-group: rows wy*32 .. +31
    int tile = wid >> 2;       // 0 or 1
    int lr = lane & 15;
    int h  = lane >> 4;
    int x7 = lane & 7;
    int bcol = lane & 7;
    int kh = (lane >> 3) & 1;

    int wbase = wy * 32;
    unsigned a_row0 = a_base + (wbase + lr) * 128;      // mf0 rows
    unsigned a_row1 = a_row0 + 16 * 128;                // mf1 rows

    if (tile == 1) {
        cp_wait0();                            // B1 landed
        asm volatile("bar.sync 1, 128;" ::: "memory");  // warps 4-7 only
    }
    unsigned bt = b_base[tile];

    float v0 = 0.f, v1 = 0.f, v2 = 0.f, v3 = 0.f;   // per-row partial sums

    #pragma unroll
    for (int gp = 0; gp < 4; gp++) {          // 4 pairs of 8-col groups
        float acc[2][2][4];                    // [group][mf][4]
        #pragma unroll
        for (int q = 0; q < 4; q++) {
            acc[0][0][q] = 0.f; acc[0][1][q] = 0.f;
            acc[1][0][q] = 0.f; acc[1][1][q] = 0.f;
        }

        unsigned b_row0 = bt + (gp * 16 + bcol) * 128;   // cols gp*16 .. +7
        unsigned b_row1 = b_row0 + 8 * 128;              // cols gp*16+8 .. +15

        #pragma unroll
        for (int s = 0; s < 4; s++) {
            unsigned swa = (unsigned)(((2 * s + h) ^ x7) << 4);
            unsigned swb = (unsigned)(((2 * s + kh) ^ x7) << 4);

            unsigned p0, p1, q0, q1;
            asm volatile("ldmatrix.sync.aligned.m8n8.x2.shared.b16 "
                         "{%0,%1}, [%2];"
                         : "=r"(p0), "=r"(p1) : "r"(b_row0 + swb));
            asm volatile("ldmatrix.sync.aligned.m8n8.x2.shared.b16 "
                         "{%0,%1}, [%2];"
                         : "=r"(q0), "=r"(q1) : "r"(b_row1 + swb));

            unsigned a0, a1, a2, a3, a4, a5, a6, a7;
            asm volatile("ldmatrix.sync.aligned.m8n8.x4.shared.b16 "
                         "{%0,%1,%2,%3}, [%4];"
                         : "=r"(a0), "=r"(a1), "=r"(a2), "=r"(a3)
                         : "r"(a_row0 + swa));
            asm volatile("ldmatrix.sync.aligned.m8n8.x4.shared.b16 "
                         "{%0,%1,%2,%3}, [%4];"
                         : "=r"(a4), "=r"(a5), "=r"(a6), "=r"(a7)
                         : "r"(a_row1 + swa));

            // 4 independent chains.
            asm volatile(
                "mma.sync.aligned.m16n8k16.row.col.f32.bf16.bf16.f32 "
                "{%0,%1,%2,%3}, {%4,%5,%6,%7}, {%8,%9}, {%0,%1,%2,%3};"
                : "+f"(acc[0][0][0]), "+f"(acc[0][0][1]),
                  "+f"(acc[0][0][2]), "+f"(acc[0][0][3])
                : "r"(a0), "r"(a1), "r"(a2), "r"(a3), "r"(p0), "r"(p1));
            asm volatile(
                "mma.sync.aligned.m16n8k16.row.col.f32.bf16.bf16.f32 "
                "{%0,%1,%2,%3}, {%4,%5,%6,%7}, {%8,%9}, {%0,%1,%2,%3};"
                : "+f"(acc[1][0][0]), "+f"(acc[1][0][1]),
                  "+f"(acc[1][0][2]), "+f"(acc[1][0][3])
                : "r"(a0), "r"(a1), "r"(a2), "r"(a3), "r"(q0), "r"(q1));
            asm volatile(
                "mma.sync.aligned.m16n8k16.row.col.f32.bf16.bf16.f32 "
                "{%0,%1,%2,%3}, {%4,%5,%6,%7}, {%8,%9}, {%0,%1,%2,%3};"
                : "+f"(acc[0][1][0]), "+f"(acc[0][1][1]),
                  "+f"(acc[0][1][2]), "+f"(acc[0][1][3])
                : "r"(a4), "r"(a5), "r"(a6), "r"(a7), "r"(p0), "r"(p1));
            asm volatile(
                "mma.sync.aligned.m16n8k16.row.col.f32.bf16.bf16.f32 "
                "{%0,%1,%2,%3}, {%4,%5,%6,%7}, {%8,%9}, {%0,%1,%2,%3};"
                : "+f"(acc[1][1][0]), "+f"(acc[1][1][1]),
                  "+f"(acc[1][1][2]), "+f"(acc[1][1][3])
                : "r"(a4), "r"(a5), "r"(a6), "r"(a7), "r"(q0), "r"(q1));
        }

        // Fused epilogue for both groups: v += t + C*max(e^4, t).
        #pragma unroll
        for (int gq = 0; gq < 2; gq++) {
            float t;
            t = ex2f(acc[gq][0][0]); v0 += fmaf(fmaxf(INV_C, t), C_MARG, t);
            t = ex2f(acc[gq][0][1]); v0 += fmaf(fmaxf(INV_C, t), C_MARG, t);
            t = ex2f(acc[gq][0][2]); v1 += fmaf(fmaxf(INV_C, t), C_MARG, t);
            t = ex2f(acc[gq][0][3]); v1 += fmaf(fmaxf(INV_C, t), C_MARG, t);
            t = ex2f(acc[gq][1][0]); v2 += fmaf(fmaxf(INV_C, t), C_MARG, t);
            t = ex2f(acc[gq][1][1]); v2 += fmaf(fmaxf(INV_C, t), C_MARG, t);
            t = ex2f(acc[gq][1][2]); v3 += fmaf(fmaxf(INV_C, t), C_MARG, t);
            t = ex2f(acc[gq][1][3]); v3 += fmaf(fmaxf(INV_C, t), C_MARG, t);
        }
    }

    // Reduce across the 4 lanes sharing each row.
    #pragma unroll
    for (int off = 1; off <= 2; off <<= 1) {
        v0 += __shfl_xor_sync(~0u, v0, off);
        v1 += __shfl_xor_sync(~0u, v1, off);
        v2 += __shfl_xor_sync(~0u, v2, off);
        v3 += __shfl_xor_sync(~0u, v3, off);
    }
    if ((lane & 3) == 0) {
        int r = rowBase + wbase + (lane >> 2);
        float* pp = g_partial + (cb0 + tile) * BATCH;
        pp[r]      = v0;
        pp[r + 8]  = v1;
        pp[r + 16] = v2;
        pp[r + 24] = v3;
    }
}

// ---------------------------------------------------------------------------
// Kernel 3: per-row loss + block sums + last-block final.
// block=1024: 8 plane-groups of 16 per row, fixed-order smem combine.
// ---------------------------------------------------------------------------
__global__ void __launch_bounds__(1024) rowloss_final_kernel(float* __restrict__ out)
{
    __shared__ float s[1024];
    __shared__ float sl[128], sb[128], ss[128];
    __shared__ unsigned isLast;

    int tid  = threadIdx.x;
    int lrow = tid & 127;
    int grp  = tid >> 7;                  // 0..7 -> planes grp*16 .. +15
    int row  = blockIdx.x * 128 + lrow;

    float rs = 0.0f;
    #pragma unroll
    for (int p = 0; p < 16; p++)
        rs += g_partial[(grp * 16 + p) * BATCH + row];
    s[tid] = rs;
    __syncthreads();

    if (tid < 128) {
        float tot = 0.0f;
        #pragma unroll
        for (int j = 0; j < 8; j++)       // fixed order
            tot += s[lrow + 128 * j];
        sl[tid] = -logf(g_pos[row] / tot + 1e-5f);
        sb[tid] = g_bpr[row];
        ss[tid] = g_sq[row];
    }
    __syncthreads();
    #pragma unroll
    for (int k = 64; k; k >>= 1) {
        if (tid < k) {
            sl[tid] += sl[tid + k];
            sb[tid] += sb[tid + k];
            ss[tid] += ss[tid + k];
        }
        __syncthreads();
    }

    if (tid == 0) {
        g_blk[blockIdx.x * 3 + 0] = sl[0];
        g_blk[blockIdx.x * 3 + 1] = sb[0];
        g_blk[blockIdx.x * 3 + 2] = ss[0];
        __threadfence();
        isLast = (atomicAdd(&g_ctr, 1u) == (unsigned)(gridDim.x - 1));
    }
    __syncthreads();

    if (isLast) {
        __threadfence();
        if (tid < 32) {
            float l = 0.0f, b = 0.0f, sq = 0.0f;
            for (int i = tid; i < 64; i += 32) {    // fixed order
                l  += g_blk[i * 3 + 0];
                b  += g_blk[i * 3 + 1];
                sq += g_blk[i * 3 + 2];
            }
            #pragma unroll
            for (int off = 16; off; off >>= 1) {
                l  += __shfl_xor_sync(~0u, l, off);
                b  += __shfl_xor_sync(~0u, b, off);
                sq += __shfl_xor_sync(~0u, sq, off);
            }
            if (tid == 0) {
                out[0] = -b / (float)BATCH;
                out[1] = 1e-4f * 0.5f * sq / (float)BATCH;
                out[2] = 0.5f * l / (float)BATCH;
                g_ctr = 0;                          // reset for next replay
            }
        }
    }
}

extern "C" void kernel_launch(void* const* d_in, const int* in_sizes, int n_in,
                              void* d_out, int out_size)
{
    const float* ut  = (const float*)d_in[0];
    const float* it  = (const float*)d_in[1];
    const int* user  = (const int*)d_in[2];
    const int* pos   = (const int*)d_in[3];
    const int* neg   = (const int*)d_in[4];

    prep_kernel<<<BATCH / 8, 128>>>(ut, it, user, pos, neg);
    dim3 grid(64, 64);
    gemm_kernel<<<grid, 256>>>();
    rowloss_final_kernel<<<64, 1024>>>((float*)d_out);
}

// round 17
// speedup vs baseline: 1.0463x; 1.0449x over previous
#include <cuda_runtime.h>
#include <cuda_bf16.h>

// LightCSCF: bpr + reg + cscf losses.
// total = e1@e2^T + e1@e1^T = e1 @ (e1+e2)^T -> 8192x8192x64 bf16 tensor GEMM
// (mma.sync; tcgen05 unavailable: harness PTX target is sm_103 without the
// 'a' feature set), fused epilogue + row-sum: g = t + C*max(e^4,t), t=ex2.
// R17 = R13 (best, 43.8us) with prep at 4 rows/warp (MLP 6->12; prep was
// measured 7.2us gather-latency-bound at occ/issue 40%).

#define BATCH 8192
#define DIM   64
#define NPLANE 128           // 64-col stripes = partial planes

#define SCALE_A 7.2134752044f      // 5 * log2(e)
#define C_MARG  0.0183156393f      // exp(-4)
#define INV_C   54.598150033f      // exp(+4)

__device__ __nv_bfloat16 g_e1h[BATCH * DIM];
__device__ __nv_bfloat16 g_fh [BATCH * DIM];
__device__ float g_pos[BATCH];
__device__ float g_bpr[BATCH];
__device__ float g_sq [BATCH];
__device__ float g_partial[NPLANE * BATCH];  // [stripe][row]
__device__ float g_blk[64 * 3];
__device__ unsigned g_ctr = 0;

__device__ __forceinline__ unsigned smem_u32(const void* p) {
    return (unsigned)__cvta_generic_to_shared(p);
}
__device__ __forceinline__ float ex2f(float x) {
    float y; asm("ex2.approx.f32 %0, %1;" : "=f"(y) : "f"(x)); return y;
}
__device__ __forceinline__ void cp16(unsigned dst, const void* src) {
    asm volatile("cp.async.cg.shared.global [%0], [%1], 16;" :: "r"(dst), "l"(src));
}
__device__ __forceinline__ void cp_commit() { asm volatile("cp.async.commit_group;"); }
__device__ __forceinline__ void cp_wait0()  { asm volatile("cp.async.wait_group 0;"); }
__device__ __forceinline__ void cp_wait1()  { asm volatile("cp.async.wait_group 1;"); }

// ---------------------------------------------------------------------------
// Kernel 1: gather + per-row stats + bf16 operand tables. 4 rows per warp
// (12 independent gathers in flight per lane -> latency halves vs 2 rows).
// ---------------------------------------------------------------------------
__global__ void __launch_bounds__(128) prep_kernel(
    const float* __restrict__ ut, const float* __restrict__ it,
    const int* __restrict__ user, const int* __restrict__ pos,
    const int* __restrict__ neg)
{
    int wid  = threadIdx.x >> 5;
    int lane = threadIdx.x & 31;
    int rb = blockIdx.x * 16 + wid * 4;

    float2 u[4], p[4], n[4];
    #pragma unroll
    for (int i = 0; i < 4; i++) {
        u[i] = ((const float2*)(ut + (long long)user[rb + i] * DIM))[lane];
        p[i] = ((const float2*)(it + (long long)pos[rb + i]  * DIM))[lane];
        n[i] = ((const float2*)(it + (long long)neg[rb + i]  * DIM))[lane];
    }

    float sup[4], sun[4], suu[4], spp[4], snn[4];
    #pragma unroll
    for (int i = 0; i < 4; i++) {
        sup[i] = u[i].x * p[i].x + u[i].y * p[i].y;
        sun[i] = u[i].x * n[i].x + u[i].y * n[i].y;
        suu[i] = u[i].x * u[i].x + u[i].y * u[i].y;
        spp[i] = p[i].x * p[i].x + p[i].y * p[i].y;
        snn[i] = n[i].x * n[i].x + n[i].y * n[i].y;
    }

    #pragma unroll
    for (int off = 16; off; off >>= 1) {
        #pragma unroll
        for (int i = 0; i < 4; i++) {
            sup[i] += __shfl_xor_sync(~0u, sup[i], off);
            sun[i] += __shfl_xor_sync(~0u, sun[i], off);
            suu[i] += __shfl_xor_sync(~0u, suu[i], off);
            spp[i] += __shfl_xor_sync(~0u, spp[i], off);
            snn[i] += __shfl_xor_sync(~0u, snn[i], off);
        }
    }

    #pragma unroll
    for (int i = 0; i < 4; i++) {
        int r = rb + i;
        float inu = 1.0f / fmaxf(sqrtf(suu[i]), 1e-12f);
        float inp = 1.0f / fmaxf(sqrtf(spp[i]), 1e-12f);
        float ax = u[i].x * inu, ay = u[i].y * inu;

        ((__nv_bfloat162*)(g_e1h + r * DIM))[lane] =
            __floats2bfloat162_rn(ax * SCALE_A, ay * SCALE_A);
        ((__nv_bfloat162*)(g_fh + r * DIM))[lane] =
            __floats2bfloat162_rn(ax + p[i].x * inp, ay + p[i].y * inp);

        if (lane == 0) {
            float sim = sup[i] * inu * inp;
            float t = __expf(sim * 5.0f);
            g_pos[r] = t + fmaxf(1.0f, t * C_MARG);
            float x = sup[i] - sun[i];
            g_bpr[r] = fminf(x, 0.0f) - log1pf(__expf(-fabsf(x)));
            g_sq[r] = suu[i] + spp[i] + snn[i];
        }
    }
}

// ---------------------------------------------------------------------------
// Kernel 2: tensor GEMM + fused epilogue + row-sum (identical to R13).
// grid (64, 64). CTA: 128 rows x two 64-col tiles. Warp w: rows (w&3)*32,
// tile (w>>2). Hoisted A frags; warps 4-7 load B1 under tile-0 compute.
// 4 CTAs/SM.
// ---------------------------------------------------------------------------
__global__ void __launch_bounds__(256, 4) gemm_kernel()
{
    __shared__ __align__(128) __nv_bfloat16 a_s[128 * DIM];     // 16KB
    __shared__ __align__(128) __nv_bfloat16 b_s[2][64 * DIM];   // 2 x 8KB

    int tid = threadIdx.x;
    int rowBase = blockIdx.y * 128;
    int cb0 = blockIdx.x * 2;

    unsigned a_base = smem_u32(a_s);
    unsigned b_base[2] = { smem_u32(b_s[0]), smem_u32(b_s[1]) };

    // Stage. Group A (all threads): A tile + B0. Group B (warps 4-7): B1.
    {
        const char* ga  = (const char*)(g_e1h + rowBase * DIM);
        const char* gb0 = (const char*)(g_fh + (cb0 * 64) * DIM);
        #pragma unroll
        for (int l = 0; l < 4; l++) {
            int i = tid + l * 256;            // 0..1023
            int r = i >> 3, c = i & 7;
            unsigned soff = (unsigned)(r * 128 + ((c ^ (r & 7)) << 4));
            cp16(a_base + soff, ga + r * 128 + c * 16);
        }
        #pragma unroll
        for (int l = 0; l < 2; l++) {
            int i = tid + l * 256;            // 0..511
            int r = i >> 3, c = i & 7;
            unsigned soff = (unsigned)(r * 128 + ((c ^ (r & 7)) << 4));
            cp16(b_base[0] + soff, gb0 + r * 128 + c * 16);
        }
        cp_commit();

        if (tid >= 128) {                     // warps 4-7 load B1
            const char* gb1 = (const char*)(g_fh + ((cb0 + 1) * 64) * DIM);
            int t2 = tid - 128;
            #pragma unroll
            for (int l = 0; l < 4; l++) {
                int i = t2 + l * 128;         // 0..511
                int r = i >> 3, c = i & 7;
                unsigned soff = (unsigned)(r * 128 + ((c ^ (r & 7)) << 4));
                cp16(b_base[1] + soff, gb1 + r * 128 + c * 16);
            }
            cp_commit();
            cp_wait1();                        // A+B0 done (B1 still flying)
        } else {
            cp_wait0();                        // only group = A+B0
        }
    }
    __syncthreads();                           // A+B0 visible to all

    int wid  = tid >> 5;
    int lane = tid & 31;
    int wy   = wid & 3;        // row-group: rows wy*32 .. +31
    int tile = wid >> 2;       // 0 or 1
    int lr = lane & 15;
    int h  = lane >> 4;
    int x7 = lane & 7;
    int bcol = lane & 7;
    int kh = (lane >> 3) & 1;

    int wbase = wy * 32;

    // Hoisted A fragments: [k-step][m-frag][4], 32 regs.
    unsigned af[4][2][4];
    #pragma unroll
    for (int s = 0; s < 4; s++) {
        unsigned sw = (unsigned)(((2 * s + h) ^ x7) << 4);
        #pragma unroll
        for (int mf = 0; mf < 2; mf++)
            asm volatile("ldmatrix.sync.aligned.m8n8.x4.shared.b16 "
                         "{%0,%1,%2,%3}, [%4];"
                         : "=r"(af[s][mf][0]), "=r"(af[s][mf][1]),
                           "=r"(af[s][mf][2]), "=r"(af[s][mf][3])
                         : "r"(a_base + (wbase + mf * 16 + lr) * 128 + sw));
    }

    if (tile == 1) {
        cp_wait0();                            // B1 landed
        asm volatile("bar.sync 1, 128;" ::: "memory");  // warps 4-7 only
    }
    unsigned bt = b_base[tile];

    float rt00 = 0.f, rm00 = 0.f, rt01 = 0.f, rm01 = 0.f;  // mf0: rows r, r+8
    float rt10 = 0.f, rm10 = 0.f, rt11 = 0.f, rm11 = 0.f;  // mf1: rows r+16, r+24

    #pragma unroll
    for (int g = 0; g < 8; g++) {             // 8 column-groups of 8
        float acc[2][4];
        #pragma unroll
        for (int mf = 0; mf < 2; mf++)
            #pragma unroll
            for (int q = 0; q < 4; q++) acc[mf][q] = 0.0f;

        unsigned b_row = bt + (g * 8 + bcol) * 128;
        #pragma unroll
        for (int s = 0; s < 4; s++) {
            unsigned swb = (unsigned)(((2 * s + kh) ^ x7) << 4);
            unsigned r0, r1;
            asm volatile("ldmatrix.sync.aligned.m8n8.x2.shared.b16 "
                         "{%0,%1}, [%2];"
                         : "=r"(r0), "=r"(r1)
                         : "r"(b_row + swb));
            #pragma unroll
            for (int mf = 0; mf < 2; mf++)
                asm volatile(
                    "mma.sync.aligned.m16n8k16.row.col.f32.bf16.bf16.f32 "
                    "{%0,%1,%2,%3}, {%4,%5,%6,%7}, {%8,%9}, {%0,%1,%2,%3};"
                    : "+f"(acc[mf][0]), "+f"(acc[mf][1]),
                      "+f"(acc[mf][2]), "+f"(acc[mf][3])
                    : "r"(af[s][mf][0]), "r"(af[s][mf][1]),
                      "r"(af[s][mf][2]), "r"(af[s][mf][3]),
                      "r"(r0), "r"(r1));
        }

        // Immediate epilogue for this 8-col group.
        float t0 = ex2f(acc[0][0]), t1 = ex2f(acc[0][1]);
        float t2 = ex2f(acc[0][2]), t3 = ex2f(acc[0][3]);
        rt00 += t0 + t1;  rm00 += fmaxf(INV_C, t0) + fmaxf(INV_C, t1);
        rt01 += t2 + t3;  rm01 += fmaxf(INV_C, t2) + fmaxf(INV_C, t3);
        float s0 = ex2f(acc[1][0]), s1 = ex2f(acc[1][1]);
        float s2 = ex2f(acc[1][2]), s3 = ex2f(acc[1][3]);
        rt10 += s0 + s1;  rm10 += fmaxf(INV_C, s0) + fmaxf(INV_C, s1);
        rt11 += s2 + s3;  rm11 += fmaxf(INV_C, s2) + fmaxf(INV_C, s3);
    }

    // Fold Σt + C*Σmax, reduce across the 4 lanes sharing each row.
    float v0 = fmaf(rm00, C_MARG, rt00);
    float v1 = fmaf(rm01, C_MARG, rt01);
    float v2 = fmaf(rm10, C_MARG, rt10);
    float v3 = fmaf(rm11, C_MARG, rt11);
    #pragma unroll
    for (int off = 1; off <= 2; off <<= 1) {
        v0 += __shfl_xor_sync(~0u, v0, off);
        v1 += __shfl_xor_sync(~0u, v1, off);
        v2 += __shfl_xor_sync(~0u, v2, off);
        v3 += __shfl_xor_sync(~0u, v3, off);
    }
    if ((lane & 3) == 0) {
        int r = rowBase + wbase + (lane >> 2);
        float* pp = g_partial + (cb0 + tile) * BATCH;
        pp[r]      = v0;
        pp[r + 8]  = v1;
        pp[r + 16] = v2;
        pp[r + 24] = v3;
    }
}

// ---------------------------------------------------------------------------
// Kernel 3: per-row loss + block sums + last-block final.
// block=1024: 8 plane-groups of 16 per row, fixed-order smem combine.
// ---------------------------------------------------------------------------
__global__ void __launch_bounds__(1024) rowloss_final_kernel(float* __restrict__ out)
{
    __shared__ float s[1024];
    __shared__ float sl[128], sb[128], ss[128];
    __shared__ unsigned isLast;

    int tid  = threadIdx.x;
    int lrow = tid & 127;
    int grp  = tid >> 7;                  // 0..7 -> planes grp*16 .. +15
    int row  = blockIdx.x * 128 + lrow;

    float rs = 0.0f;
    #pragma unroll
    for (int p = 0; p < 16; p++)
        rs += g_partial[(grp * 16 + p) * BATCH + row];
    s[tid] = rs;
    __syncthreads();

    if (tid < 128) {
        float tot = 0.0f;
        #pragma unroll
        for (int j = 0; j < 8; j++)       // fixed order
            tot += s[lrow + 128 * j];
        sl[tid] = -logf(g_pos[row] / tot + 1e-5f);
        sb[tid] = g_bpr[row];
        ss[tid] = g_sq[row];
    }
    __syncthreads();
    #pragma unroll
    for (int k = 64; k; k >>= 1) {
        if (tid < k) {
            sl[tid] += sl[tid + k];
            sb[tid] += sb[tid + k];
            ss[tid] += ss[tid + k];
        }
        __syncthreads();
    }

    if (tid == 0) {
        g_blk[blockIdx.x * 3 + 0] = sl[0];
        g_blk[blockIdx.x * 3 + 1] = sb[0];
        g_blk[blockIdx.x * 3 + 2] = ss[0];
        __threadfence();
        isLast = (atomicAdd(&g_ctr, 1u) == (unsigned)(gridDim.x - 1));
    }
    __syncthreads();

    if (isLast) {
        __threadfence();
        if (tid < 32) {
            float l = 0.0f, b = 0.0f, sq = 0.0f;
            for (int i = tid; i < 64; i += 32) {    // fixed order
                l  += g_blk[i * 3 + 0];
                b  += g_blk[i * 3 + 1];
                sq += g_blk[i * 3 + 2];
            }
            #pragma unroll
            for (int off = 16; off; off >>= 1) {
                l  += __shfl_xor_sync(~0u, l, off);
                b  += __shfl_xor_sync(~0u, b, off);
                sq += __shfl_xor_sync(~0u, sq, off);
            }
            if (tid == 0) {
                out[0] = -b / (float)BATCH;
                out[1] = 1e-4f * 0.5f * sq / (float)BATCH;
                out[2] = 0.5f * l / (float)BATCH;
                g_ctr = 0;                          // reset for next replay
            }
        }
    }
}

extern "C" void kernel_launch(void* const* d_in, const int* in_sizes, int n_in,
                              void* d_out, int out_size)
{
    const float* ut  = (const float*)d_in[0];
    const float* it  = (const float*)d_in[1];
    const int* user  = (const int*)d_in[2];
    const int* pos   = (const int*)d_in[3];
    const int* neg   = (const int*)d_in[4];

    prep_kernel<<<BATCH / 16, 128>>>(ut, it, user, pos, neg);
    dim3 grid(64, 64);
    gemm_kernel<<<grid, 256>>>();
    rowloss_final_kernel<<<64, 1024>>>((float*)d_out);
}